// round 1
// baseline (speedup 1.0000x reference)
#include <cuda_runtime.h>
#include <math.h>

#define Bsz 64
#define Tsz 2000
#define Esz 512
#define Rsz 1024
#define Asz 512
#define Msz 8

// ---------------- scratch (reused across sequential stages) ----------------
__device__ float g_part[8 * Bsz * Asz];   // split-K partials (1 MB), reused 3x
__device__ float g_x1[Bsz * Asz];
__device__ float g_x[Bsz * Asz];
__device__ float g_wmix[Bsz * Msz];
__device__ float g_loc[Bsz * Msz];
__device__ float g_scale[Bsz * Msz];

// ---------------- split-K tiled SGEMM: C_part[ks][64][N] = A(64,K)*W(N,K)^T --
// grid: (N/64, KS), block: 256. Optional tanh applied to A elements on load.
__global__ void gemm_part_kernel(const float* __restrict__ Ain,
                                 const float* __restrict__ W,
                                 float* __restrict__ part,
                                 int N, int K, int KCH, int tanh_in) {
    __shared__ float As[64][33];
    __shared__ float Ws[64][33];

    const int nt = blockIdx.x;
    const int ks = blockIdx.y;
    const int nbase = nt * 64;
    const int k0 = ks * KCH;

    const int tx = threadIdx.x & 15;   // 0..15 -> 4 output cols
    const int ty = threadIdx.x >> 4;   // 0..15 -> 4 output rows
    const int lane = threadIdx.x & 31;
    const int wrp = threadIdx.x >> 5;  // 8 warps

    float acc[4][4];
#pragma unroll
    for (int i = 0; i < 4; i++)
#pragma unroll
        for (int j = 0; j < 4; j++) acc[i][j] = 0.0f;

    for (int kk = 0; kk < KCH; kk += 32) {
        const int kc = k0 + kk + lane;
#pragma unroll
        for (int r = wrp; r < 64; r += 8) {
            float v = Ain[r * K + kc];
            if (tanh_in) v = tanhf(v);
            As[r][lane] = v;
            Ws[r][lane] = W[(nbase + r) * K + kc];
        }
        __syncthreads();
#pragma unroll
        for (int k = 0; k < 32; k++) {
            float a[4], w[4];
#pragma unroll
            for (int i = 0; i < 4; i++) a[i] = As[ty * 4 + i][k];
#pragma unroll
            for (int j = 0; j < 4; j++) w[j] = Ws[tx * 4 + j][k];
#pragma unroll
            for (int i = 0; i < 4; i++)
#pragma unroll
                for (int j = 0; j < 4; j++) acc[i][j] = fmaf(a[i], w[j], acc[i][j]);
        }
        __syncthreads();
    }

#pragma unroll
    for (int i = 0; i < 4; i++) {
        const int b = ty * 4 + i;
#pragma unroll
        for (int j = 0; j < 4; j++) {
            const int n = nbase + tx * 4 + j;
            part[(ks * 64 + b) * N + n] = acc[i][j];
        }
    }
}

// ---------------- reduce split-K partials, optional bias + tanh -------------
__global__ void reduce_kernel(const float* __restrict__ part,
                              const float* __restrict__ bias,
                              float* __restrict__ out,
                              int N, int KS, int act_tanh) {
    int idx = blockIdx.x * blockDim.x + threadIdx.x;
    if (idx >= Bsz * N) return;
    int b = idx / N, n = idx - b * N;
    float s = 0.0f;
    for (int k = 0; k < KS; k++) s += part[(k * 64 + b) * N + n];
    if (bias) s += bias[n];
    if (act_tanh) s = tanhf(s);
    out[idx] = s;
}

// ---------------- head: y = x@Wlin^T + blin -> wmix/loc/scale ----------------
// grid: 64, block: 768 (24 warps, one per output of y)
__global__ void head_kernel(const float* __restrict__ x,
                            const float* __restrict__ Wlin,
                            const float* __restrict__ blin,
                            const float* __restrict__ prev,
                            float* __restrict__ out_loc) {
    const int b = blockIdx.x;
    const int w = threadIdx.x >> 5;
    const int lane = threadIdx.x & 31;
    __shared__ float ys[24];

    if (w < 24) {
        float s = 0.0f;
        const float* xr = x + b * Asz;
        const float* wr = Wlin + w * Asz;
        for (int k = lane; k < Asz; k += 32) s = fmaf(xr[k], wr[k], s);
#pragma unroll
        for (int off = 16; off > 0; off >>= 1)
            s += __shfl_down_sync(0xffffffffu, s, off);
        if (lane == 0) ys[w] = s + blin[w];
    }
    __syncthreads();

    if (threadIdx.x < Msz) {
        const int m = threadIdx.x;
        float wv = ys[m];
        float dv = ys[Msz + m];
        float sv = ys[2 * Msz + m];
        float wmix = 1.0f / (1.0f + expf(-wv));
        float loc = prev[b * Msz + m] + 1.0f / (1.0f + expf(-dv));
        float scl = 1.0f / (1.0f + expf(-sv)) * 2.0f + 1.0f;
        g_wmix[b * Msz + m] = wmix;
        g_loc[b * Msz + m] = loc;
        g_scale[b * Msz + m] = scl;
        out_loc[b * Msz + m] = loc;
    }
}

// ---------------- alignment + masked softmax per batch row -------------------
// grid: 64, block: 1024. Row (T=2000) kept resident in smem.
__global__ void align_softmax_kernel(const unsigned char* __restrict__ mask,
                                     float* __restrict__ out_w) {
    const int b = blockIdx.x;
    const int tid = threadIdx.x;
    __shared__ float sal[Tsz];
    __shared__ float red[32];
    __shared__ float sw[Msz], sl[Msz], ss[Msz];

    if (tid < Msz) {
        sw[tid] = g_wmix[b * Msz + tid];
        sl[tid] = g_loc[b * Msz + tid];
        ss[tid] = g_scale[b * Msz + tid];
    }
    __syncthreads();

    float lmax = -1e30f;
    for (int t = tid; t < Tsz; t += blockDim.x) {
        float al = 0.0f;
        float ft = (float)t;
#pragma unroll
        for (int m = 0; m < Msz; m++) {
            float d = sl[m] - ft;
            float sc = ss[m];
            float z = 0.5f * (erff((d + 0.5f) * sc) - erff((d - 0.5f) * sc));
            al = fmaf(z, sw[m], al);
        }
        if (mask[b * Tsz + t]) al = 0.0f;
        sal[t] = al;
        lmax = fmaxf(lmax, al);
    }
    // block max
    const int lane = tid & 31, wrp = tid >> 5;
#pragma unroll
    for (int off = 16; off > 0; off >>= 1)
        lmax = fmaxf(lmax, __shfl_xor_sync(0xffffffffu, lmax, off));
    if (lane == 0) red[wrp] = lmax;
    __syncthreads();
    if (wrp == 0) {
        float v = (lane < (blockDim.x >> 5)) ? red[lane] : -1e30f;
#pragma unroll
        for (int off = 16; off > 0; off >>= 1)
            v = fmaxf(v, __shfl_xor_sync(0xffffffffu, v, off));
        if (lane == 0) red[0] = v;
    }
    __syncthreads();
    const float mx = red[0];
    __syncthreads();

    float lsum = 0.0f;
    for (int t = tid; t < Tsz; t += blockDim.x) {
        float e = __expf(sal[t] - mx);
        sal[t] = e;
        lsum += e;
    }
#pragma unroll
    for (int off = 16; off > 0; off >>= 1)
        lsum += __shfl_xor_sync(0xffffffffu, lsum, off);
    if (lane == 0) red[wrp] = lsum;
    __syncthreads();
    if (wrp == 0) {
        float v = (lane < (blockDim.x >> 5)) ? red[lane] : 0.0f;
#pragma unroll
        for (int off = 16; off > 0; off >>= 1)
            v += __shfl_xor_sync(0xffffffffu, v, off);
        if (lane == 0) red[0] = v;
    }
    __syncthreads();
    const float inv = 1.0f / red[0];

    for (int t = tid; t < Tsz; t += blockDim.x)
        out_w[b * Tsz + t] = sal[t] * inv;
}

// ---------------- context partials: T split by 8 -----------------------------
// grid: (8, 64), block: 128 (float4 per thread covers all E=512)
#define TSPLIT 8
#define TCHUNK (Tsz / TSPLIT)
__global__ void ctx_part_kernel(const float* __restrict__ mem,
                                const float* __restrict__ wts,
                                float* __restrict__ part) {
    const int s = blockIdx.x;
    const int b = blockIdx.y;
    const int e4 = threadIdx.x;   // 0..127
    const float4* mrow = (const float4*)(mem + (size_t)b * Tsz * Esz);
    const float* wr = wts + b * Tsz;

    float4 acc = make_float4(0.f, 0.f, 0.f, 0.f);
    const int t0 = s * TCHUNK;
#pragma unroll 4
    for (int t = t0; t < t0 + TCHUNK; t++) {
        float w = wr[t];
        float4 v = mrow[t * (Esz / 4) + e4];
        acc.x = fmaf(w, v.x, acc.x);
        acc.y = fmaf(w, v.y, acc.y);
        acc.z = fmaf(w, v.z, acc.z);
        acc.w = fmaf(w, v.w, acc.w);
    }
    ((float4*)part)[((s * 64 + b) * Esz) / 4 + e4] = acc;
}

__global__ void ctx_reduce_kernel(const float* __restrict__ part,
                                  float* __restrict__ out_ctx) {
    int idx = blockIdx.x * blockDim.x + threadIdx.x;
    if (idx >= Bsz * Esz) return;
    int b = idx / Esz, e = idx - b * Esz;
    float s = 0.0f;
#pragma unroll
    for (int k = 0; k < TSPLIT; k++) s += part[(k * 64 + b) * Esz + e];
    out_ctx[idx] = s;
}

// ---------------- launch ------------------------------------------------------
extern "C" void kernel_launch(void* const* d_in, const int* in_sizes, int n_in,
                              void* d_out, int out_size) {
    const float* ash  = (const float*)d_in[0];          // (64,1024)
    const float* mem  = (const float*)d_in[1];          // (64,2000,512)
    const float* prev = (const float*)d_in[2];          // (64,1,8)
    const unsigned char* mask = (const unsigned char*)d_in[3]; // (64,2000) all-false
    const float* W1   = (const float*)d_in[4];          // (512,1024)
    const float* b1   = (const float*)d_in[5];          // (512,)
    const float* W2   = (const float*)d_in[6];          // (512,512)
    const float* Wlin = (const float*)d_in[7];          // (24,512)
    const float* blin = (const float*)d_in[8];          // (24,)

    float* out     = (float*)d_out;
    float* out_ctx = out;                                // (64,512)
    float* out_w   = out + Bsz * Esz;                    // (64,2000)
    float* out_loc = out_w + Bsz * Tsz;                  // (64,8)

    float *part, *x1, *x;
    cudaGetSymbolAddress((void**)&part, g_part);
    cudaGetSymbolAddress((void**)&x1, g_x1);
    cudaGetSymbolAddress((void**)&x, g_x);

    // stage 1: x1 = tanh(ash) @ W1^T + b1   (K=1024, split 8)
    gemm_part_kernel<<<dim3(Asz / 64, 8), 256>>>(ash, W1, part, Asz, Rsz, Rsz / 8, 1);
    reduce_kernel<<<(Bsz * Asz + 255) / 256, 256>>>(part, b1, x1, Asz, 8, 0);

    // stage 2: x = tanh(x1 @ W2^T)          (K=512, split 8)
    gemm_part_kernel<<<dim3(Asz / 64, 8), 256>>>(x1, W2, part, Asz, Asz, Asz / 8, 0);
    reduce_kernel<<<(Bsz * Asz + 255) / 256, 256>>>(part, nullptr, x, Asz, 8, 1);

    // head: y -> wmix / loc / scale  (also writes loc output)
    head_kernel<<<Bsz, 768>>>(x, Wlin, blin, prev, out_loc);

    // alignment + softmax -> attention_weights
    align_softmax_kernel<<<Bsz, 1024>>>(mask, out_w);

    // context = weights^T * memory  (HBM-bound phase)
    ctx_part_kernel<<<dim3(TSPLIT, Bsz), 128>>>(mem, out_w, part);
    ctx_reduce_kernel<<<(Bsz * Esz + 255) / 256, 256>>>(part, out_ctx);
}

// round 3
// speedup vs baseline: 1.5105x; 1.5105x over previous
#include <cuda_runtime.h>
#include <math.h>

#define Bsz 64
#define Tsz 2000
#define Esz 512
#define Rsz 1024
#define Asz 512
#define Msz 8
#define TSPLIT 20
#define TCHUNK (Tsz / TSPLIT)

// ---------------- scratch -----------------------------------------------------
__device__ float g_part1[8 * Bsz * Asz];        // stage-1 split-K partials
__device__ float g_part2[8 * Bsz * Asz];        // stage-2 split-K partials
__device__ float g_cpart[TSPLIT * Bsz * Esz];   // context partials (5 MB)
__device__ float g_wmix[Bsz * Msz];
__device__ float g_loc[Bsz * Msz];
__device__ float g_scale[Bsz * Msz];
__device__ int   g_ctr[Bsz];                    // zero-init; reset each replay

// ---------------- stage 1: part1[ks] = tanh(ash) @ W1^T (split-K) ------------
// grid (Asz/64, 8), block 256
__global__ void gemm1_kernel(const float* __restrict__ Ain,
                             const float* __restrict__ W) {
    __shared__ float As[64][33];
    __shared__ float Ws[64][33];
    const int nbase = blockIdx.x * 64;
    const int k0 = blockIdx.y * (Rsz / 8);
    const int tx = threadIdx.x & 15, ty = threadIdx.x >> 4;
    const int lane = threadIdx.x & 31, wrp = threadIdx.x >> 5;

    float acc[4][4] = {};
    for (int kk = 0; kk < Rsz / 8; kk += 32) {
        const int kc = k0 + kk + lane;
#pragma unroll
        for (int r = wrp; r < 64; r += 8) {
            As[r][lane] = tanhf(Ain[r * Rsz + kc]);
            Ws[r][lane] = W[(nbase + r) * Rsz + kc];
        }
        __syncthreads();
#pragma unroll
        for (int k = 0; k < 32; k++) {
            float a[4], w[4];
#pragma unroll
            for (int i = 0; i < 4; i++) a[i] = As[ty * 4 + i][k];
#pragma unroll
            for (int j = 0; j < 4; j++) w[j] = Ws[tx * 4 + j][k];
#pragma unroll
            for (int i = 0; i < 4; i++)
#pragma unroll
                for (int j = 0; j < 4; j++) acc[i][j] = fmaf(a[i], w[j], acc[i][j]);
        }
        __syncthreads();
    }
#pragma unroll
    for (int i = 0; i < 4; i++)
#pragma unroll
        for (int j = 0; j < 4; j++)
            g_part1[(blockIdx.y * 64 + ty * 4 + i) * Asz + nbase + tx * 4 + j] = acc[i][j];
}

// ---------------- stage 2: part2[ks] = (sum part1 + b1) @ W2^T (split-K) ------
// A-tile loader fuses the stage-1 reduce + bias. grid (Asz/64, 8), block 256
__global__ void gemm2_kernel(const float* __restrict__ W,
                             const float* __restrict__ b1) {
    __shared__ float As[64][33];
    __shared__ float Ws[64][33];
    const int nbase = blockIdx.x * 64;
    const int k0 = blockIdx.y * (Asz / 8);
    const int tx = threadIdx.x & 15, ty = threadIdx.x >> 4;
    const int lane = threadIdx.x & 31, wrp = threadIdx.x >> 5;

    float acc[4][4] = {};
    for (int kk = 0; kk < Asz / 8; kk += 32) {
        const int kc = k0 + kk + lane;
        const float bb = b1[kc];
#pragma unroll
        for (int r = wrp; r < 64; r += 8) {
            float s = bb;
#pragma unroll
            for (int p = 0; p < 8; p++) s += g_part1[(p * 64 + r) * Asz + kc];
            As[r][lane] = s;
            Ws[r][lane] = W[(nbase + r) * Asz + kc];
        }
        __syncthreads();
#pragma unroll
        for (int k = 0; k < 32; k++) {
            float a[4], w[4];
#pragma unroll
            for (int i = 0; i < 4; i++) a[i] = As[ty * 4 + i][k];
#pragma unroll
            for (int j = 0; j < 4; j++) w[j] = Ws[tx * 4 + j][k];
#pragma unroll
            for (int i = 0; i < 4; i++)
#pragma unroll
                for (int j = 0; j < 4; j++) acc[i][j] = fmaf(a[i], w[j], acc[i][j]);
        }
        __syncthreads();
    }
#pragma unroll
    for (int i = 0; i < 4; i++)
#pragma unroll
        for (int j = 0; j < 4; j++)
            g_part2[(blockIdx.y * 64 + ty * 4 + i) * Asz + nbase + tx * 4 + j] = acc[i][j];
}

// ---------------- head: x = tanh(sum part2); y = x@Wlin^T + blin --------------
// grid 64, block 768 (24 warps = 24 outputs of y)
__global__ void head_kernel(const float* __restrict__ Wlin,
                            const float* __restrict__ blin,
                            const float* __restrict__ prev,
                            float* __restrict__ out_loc) {
    const int b = blockIdx.x;
    const int tid = threadIdx.x;
    const int w = tid >> 5, lane = tid & 31;
    __shared__ float sx[Asz];
    __shared__ float ys[24];

    for (int i = tid; i < Asz; i += 768) {
        float s = 0.0f;
#pragma unroll
        for (int p = 0; p < 8; p++) s += g_part2[(p * 64 + b) * Asz + i];
        sx[i] = tanhf(s);
    }
    __syncthreads();

    if (w < 24) {
        float s = 0.0f;
        const float* wr = Wlin + w * Asz;
        for (int k = lane; k < Asz; k += 32) s = fmaf(sx[k], wr[k], s);
#pragma unroll
        for (int off = 16; off > 0; off >>= 1)
            s += __shfl_down_sync(0xffffffffu, s, off);
        if (lane == 0) ys[w] = s + blin[w];
    }
    __syncthreads();

    if (tid < Msz) {
        const int m = tid;
        float wmix = 1.0f / (1.0f + expf(-ys[m]));
        float loc = prev[b * Msz + m] + 1.0f / (1.0f + expf(-ys[Msz + m]));
        float scl = 1.0f / (1.0f + expf(-ys[2 * Msz + m])) * 2.0f + 1.0f;
        g_wmix[b * Msz + m] = wmix;
        g_loc[b * Msz + m] = loc;
        g_scale[b * Msz + m] = scl;
        out_loc[b * Msz + m] = loc;
    }
}

// ---------------- alignment + masked softmax ----------------------------------
// grid 64, block 1024
__global__ void align_softmax_kernel(const unsigned char* __restrict__ mask,
                                     float* __restrict__ out_w) {
    const int b = blockIdx.x;
    const int tid = threadIdx.x;
    __shared__ float sal[Tsz];
    __shared__ float red[32];
    __shared__ float sw[Msz], sl[Msz], ss[Msz];

    if (tid < Msz) {
        sw[tid] = g_wmix[b * Msz + tid];
        sl[tid] = g_loc[b * Msz + tid];
        ss[tid] = g_scale[b * Msz + tid];
    }
    __syncthreads();

    float lmax = -1e30f;
    for (int t = tid; t < Tsz; t += blockDim.x) {
        float al = 0.0f;
        float ft = (float)t;
#pragma unroll
        for (int m = 0; m < Msz; m++) {
            float d = sl[m] - ft;
            float sc = ss[m];
            float z = 0.5f * (erff((d + 0.5f) * sc) - erff((d - 0.5f) * sc));
            al = fmaf(z, sw[m], al);
        }
        if (mask[b * Tsz + t]) al = 0.0f;
        sal[t] = al;
        lmax = fmaxf(lmax, al);
    }
    const int lane = tid & 31, wrp = tid >> 5;
#pragma unroll
    for (int off = 16; off > 0; off >>= 1)
        lmax = fmaxf(lmax, __shfl_xor_sync(0xffffffffu, lmax, off));
    if (lane == 0) red[wrp] = lmax;
    __syncthreads();
    if (wrp == 0) {
        float v = red[lane];
#pragma unroll
        for (int off = 16; off > 0; off >>= 1)
            v = fmaxf(v, __shfl_xor_sync(0xffffffffu, v, off));
        if (lane == 0) red[0] = v;
    }
    __syncthreads();
    const float mx = red[0];
    __syncthreads();

    float lsum = 0.0f;
    for (int t = tid; t < Tsz; t += blockDim.x) {
        float e = __expf(sal[t] - mx);
        sal[t] = e;
        lsum += e;
    }
#pragma unroll
    for (int off = 16; off > 0; off >>= 1)
        lsum += __shfl_xor_sync(0xffffffffu, lsum, off);
    if (lane == 0) red[wrp] = lsum;
    __syncthreads();
    if (wrp == 0) {
        float v = red[lane];
#pragma unroll
        for (int off = 16; off > 0; off >>= 1)
            v += __shfl_xor_sync(0xffffffffu, v, off);
        if (lane == 0) red[0] = v;
    }
    __syncthreads();
    const float inv = 1.0f / red[0];

    for (int t = tid; t < Tsz; t += blockDim.x)
        out_w[b * Tsz + t] = sal[t] * inv;
}

// ---------------- context: partials + last-block reduce ------------------------
// grid (TSPLIT, Bsz), block 128; each thread = one float4 of E
__global__ void ctx_kernel(const float* __restrict__ mem,
                           const float* __restrict__ wts,
                           float* __restrict__ out_ctx) {
    const int s = blockIdx.x;
    const int b = blockIdx.y;
    const int e4 = threadIdx.x;
    const float4* mrow = (const float4*)(mem + (size_t)b * Tsz * Esz);
    const float* wr = wts + b * Tsz;

    float4 acc = make_float4(0.f, 0.f, 0.f, 0.f);
    const int t0 = s * TCHUNK;
#pragma unroll 4
    for (int t = t0; t < t0 + TCHUNK; t++) {
        float w = __ldg(wr + t);
        float4 v = __ldcs(mrow + t * (Esz / 4) + e4);
        acc.x = fmaf(w, v.x, acc.x);
        acc.y = fmaf(w, v.y, acc.y);
        acc.z = fmaf(w, v.z, acc.z);
        acc.w = fmaf(w, v.w, acc.w);
    }
    ((float4*)g_cpart)[(s * Bsz + b) * (Esz / 4) + e4] = acc;

    // Make this block's partial globally visible, THEN make sure every warp of
    // this block has done so, THEN signal the counter. (R2 bug: thread 0 could
    // increment the counter before sibling warps finished storing.)
    __threadfence();
    __syncthreads();

    __shared__ int done;
    if (threadIdx.x == 0) done = atomicAdd(&g_ctr[b], 1);
    __syncthreads();

    if (done == TSPLIT - 1) {
        __threadfence();  // acquire side: order partial loads after counter read
        float4 sum = make_float4(0.f, 0.f, 0.f, 0.f);
#pragma unroll
        for (int p = 0; p < TSPLIT; p++) {
            float4 v = ((const float4*)g_cpart)[(p * Bsz + b) * (Esz / 4) + e4];
            sum.x += v.x; sum.y += v.y; sum.z += v.z; sum.w += v.w;
        }
        ((float4*)out_ctx)[b * (Esz / 4) + e4] = sum;
        if (threadIdx.x == 0) g_ctr[b] = 0;  // reset for next replay
    }
}

// ---------------- launch --------------------------------------------------------
extern "C" void kernel_launch(void* const* d_in, const int* in_sizes, int n_in,
                              void* d_out, int out_size) {
    const float* ash  = (const float*)d_in[0];
    const float* mem  = (const float*)d_in[1];
    const float* prev = (const float*)d_in[2];
    const unsigned char* mask = (const unsigned char*)d_in[3];
    const float* W1   = (const float*)d_in[4];
    const float* b1   = (const float*)d_in[5];
    const float* W2   = (const float*)d_in[6];
    const float* Wlin = (const float*)d_in[7];
    const float* blin = (const float*)d_in[8];

    float* out     = (float*)d_out;
    float* out_ctx = out;
    float* out_w   = out + Bsz * Esz;
    float* out_loc = out_w + Bsz * Tsz;

    gemm1_kernel<<<dim3(Asz / 64, 8), 256>>>(ash, W1);
    gemm2_kernel<<<dim3(Asz / 64, 8), 256>>>(W2, b1);
    head_kernel<<<Bsz, 768>>>(Wlin, blin, prev, out_loc);
    align_softmax_kernel<<<Bsz, 1024>>>(mask, out_w);
    ctx_kernel<<<dim3(TSPLIT, Bsz), 128>>>(mem, out_w, out_ctx);
}

// round 4
// speedup vs baseline: 1.6874x; 1.1172x over previous
#include <cuda_runtime.h>
#include <math.h>

#define Bsz 64
#define Tsz 2000
#define Esz 512
#define Rsz 1024
#define Asz 512
#define Msz 8
#define KS 16
#define TSPLIT 20
#define TCHUNK (Tsz / TSPLIT)

// ---------------- scratch -----------------------------------------------------
__device__ float g_part1[KS * Bsz * Asz];       // stage-1 split-K partials (2 MB)
__device__ float g_part2[KS * Bsz * Asz];       // stage-2 split-K partials (2 MB)
__device__ float g_cpart[TSPLIT * Bsz * Esz];   // context partials
__device__ float g_esum[TSPLIT * Bsz];          // exp-sum partials
__device__ float g_wmix[Bsz * Msz];
__device__ float g_loc[Bsz * Msz];
__device__ float g_scale[Bsz * Msz];
__device__ int   g_ctr[Bsz];                    // zero-init; reset by last block

// ---------------- stage 1: part1[ks] = tanh(ash) @ W1^T (split-K 16) ----------
// grid (Asz/64, KS), block 256
__global__ void gemm1_kernel(const float* __restrict__ Ain,
                             const float* __restrict__ W) {
    __shared__ float As[64][33];
    __shared__ float Ws[64][33];
    const int nbase = blockIdx.x * 64;
    const int k0 = blockIdx.y * (Rsz / KS);
    const int tx = threadIdx.x & 15, ty = threadIdx.x >> 4;
    const int lane = threadIdx.x & 31, wrp = threadIdx.x >> 5;

    float acc[4][4] = {};
    for (int kk = 0; kk < Rsz / KS; kk += 32) {
        const int kc = k0 + kk + lane;
#pragma unroll
        for (int r = wrp; r < 64; r += 8) {
            As[r][lane] = tanhf(Ain[r * Rsz + kc]);
            Ws[r][lane] = W[(nbase + r) * Rsz + kc];
        }
        __syncthreads();
#pragma unroll
        for (int k = 0; k < 32; k++) {
            float a[4], w[4];
#pragma unroll
            for (int i = 0; i < 4; i++) a[i] = As[ty * 4 + i][k];
#pragma unroll
            for (int j = 0; j < 4; j++) w[j] = Ws[tx * 4 + j][k];
#pragma unroll
            for (int i = 0; i < 4; i++)
#pragma unroll
                for (int j = 0; j < 4; j++) acc[i][j] = fmaf(a[i], w[j], acc[i][j]);
        }
        __syncthreads();
    }
#pragma unroll
    for (int i = 0; i < 4; i++)
#pragma unroll
        for (int j = 0; j < 4; j++)
            g_part1[(blockIdx.y * 64 + ty * 4 + i) * Asz + nbase + tx * 4 + j] = acc[i][j];
}

// ---------------- stage 2: part2[ks] = (sum part1 + b1) @ W2^T (split-K 16) ---
// grid (Asz/64, KS), block 256; loader fuses the stage-1 reduce + bias
__global__ void gemm2_kernel(const float* __restrict__ W,
                             const float* __restrict__ b1) {
    __shared__ float As[64][33];
    __shared__ float Ws[64][33];
    const int nbase = blockIdx.x * 64;
    const int k0 = blockIdx.y * (Asz / KS);
    const int tx = threadIdx.x & 15, ty = threadIdx.x >> 4;
    const int lane = threadIdx.x & 31, wrp = threadIdx.x >> 5;

    float acc[4][4] = {};
    for (int kk = 0; kk < Asz / KS; kk += 32) {
        const int kc = k0 + kk + lane;
        const float bb = b1[kc];
#pragma unroll
        for (int r = wrp; r < 64; r += 8) {
            float s = bb;
#pragma unroll
            for (int p = 0; p < KS; p++) s += g_part1[(p * 64 + r) * Asz + kc];
            As[r][lane] = s;
            Ws[r][lane] = W[(nbase + r) * Asz + kc];
        }
        __syncthreads();
#pragma unroll
        for (int k = 0; k < 32; k++) {
            float a[4], w[4];
#pragma unroll
            for (int i = 0; i < 4; i++) a[i] = As[ty * 4 + i][k];
#pragma unroll
            for (int j = 0; j < 4; j++) w[j] = Ws[tx * 4 + j][k];
#pragma unroll
            for (int i = 0; i < 4; i++)
#pragma unroll
                for (int j = 0; j < 4; j++) acc[i][j] = fmaf(a[i], w[j], acc[i][j]);
        }
        __syncthreads();
    }
#pragma unroll
    for (int i = 0; i < 4; i++)
#pragma unroll
        for (int j = 0; j < 4; j++)
            g_part2[(blockIdx.y * 64 + ty * 4 + i) * Asz + nbase + tx * 4 + j] = acc[i][j];
}

// ---------------- head: x = tanh(sum part2); y = x@Wlin^T + blin --------------
// grid 64, block 768 (24 warps = 24 outputs of y)
__global__ void head_kernel(const float* __restrict__ Wlin,
                            const float* __restrict__ blin,
                            const float* __restrict__ prev,
                            float* __restrict__ out_loc) {
    const int b = blockIdx.x;
    const int tid = threadIdx.x;
    const int w = tid >> 5, lane = tid & 31;
    __shared__ float sx[Asz];
    __shared__ float ys[24];

    for (int i = tid; i < Asz; i += 768) {
        float s = 0.0f;
#pragma unroll
        for (int p = 0; p < KS; p++) s += g_part2[(p * 64 + b) * Asz + i];
        sx[i] = tanhf(s);
    }
    __syncthreads();

    if (w < 24) {
        float s = 0.0f;
        const float* wr = Wlin + w * Asz;
        for (int k = lane; k < Asz; k += 32) s = fmaf(sx[k], wr[k], s);
#pragma unroll
        for (int off = 16; off > 0; off >>= 1)
            s += __shfl_down_sync(0xffffffffu, s, off);
        if (lane == 0) ys[w] = s + blin[w];
    }
    __syncthreads();

    if (tid < Msz) {
        const int m = tid;
        float wmix = 1.0f / (1.0f + expf(-ys[m]));
        float loc = prev[b * Msz + m] + 1.0f / (1.0f + expf(-ys[Msz + m]));
        float scl = 1.0f / (1.0f + expf(-ys[2 * Msz + m])) * 2.0f + 1.0f;
        g_wmix[b * Msz + m] = wmix;
        g_loc[b * Msz + m] = loc;
        g_scale[b * Msz + m] = scl;
        out_loc[b * Msz + m] = loc;
    }
}

// ---------------- fused alignment + exp + context + softmax-normalize ----------
// grid (TSPLIT, Bsz), block 128.
// Softmax WITHOUT max-subtraction: alignment in [0,8] so exp(a) <= e^8, safe,
// and exp(a)/sum(exp(a)) is mathematically identical to max-subtracted softmax.
__global__ void ctx_fused_kernel(const float* __restrict__ mem,
                                 const unsigned char* __restrict__ mask,
                                 float* __restrict__ out_w,
                                 float* __restrict__ out_ctx) {
    const int s = blockIdx.x;
    const int b = blockIdx.y;
    const int tid = threadIdx.x;
    const int lane = tid & 31, wrp = tid >> 5;
    const int t0 = s * TCHUNK;

    __shared__ float ex[TCHUNK];
    __shared__ float sw[Msz], sl[Msz], ss[Msz];
    __shared__ float red[4];

    if (tid < Msz) {
        sw[tid] = g_wmix[b * Msz + tid];
        sl[tid] = g_loc[b * Msz + tid];
        ss[tid] = g_scale[b * Msz + tid];
    }
    __syncthreads();

    // alignment + exp for this block's t-chunk (unnormalized weights)
    if (tid < TCHUNK) {
        const int t = t0 + tid;
        float al = 0.0f;
        const float ft = (float)t;
#pragma unroll
        for (int m = 0; m < Msz; m++) {
            float d = sl[m] - ft;
            float sc = ss[m];
            float z = 0.5f * (erff((d + 0.5f) * sc) - erff((d - 0.5f) * sc));
            al = fmaf(z, sw[m], al);
        }
        if (mask[b * Tsz + t]) al = 0.0f;   // reference: masked -> alignment 0 (exp -> 1)
        float e = __expf(al);
        ex[tid] = e;
        out_w[b * Tsz + t] = e;             // rescaled by the last block
    }
    __syncthreads();

    // block partial exp-sum
    {
        float v = (tid < TCHUNK) ? ex[tid] : 0.0f;
#pragma unroll
        for (int off = 16; off > 0; off >>= 1)
            v += __shfl_xor_sync(0xffffffffu, v, off);
        if (lane == 0) red[wrp] = v;
        __syncthreads();
        if (tid == 0) g_esum[s * Bsz + b] = red[0] + red[1] + red[2] + red[3];
    }

    // HBM-bound streaming: acc_e4 = sum_t ex[t] * mem[b,t,e4]
    const float4* mrow = (const float4*)(mem + (size_t)b * Tsz * Esz);
    float4 acc = make_float4(0.f, 0.f, 0.f, 0.f);
#pragma unroll 4
    for (int i = 0; i < TCHUNK; i++) {
        float w = ex[i];
        float4 v = __ldcs(mrow + (t0 + i) * (Esz / 4) + tid);
        acc.x = fmaf(w, v.x, acc.x);
        acc.y = fmaf(w, v.y, acc.y);
        acc.z = fmaf(w, v.z, acc.z);
        acc.w = fmaf(w, v.w, acc.w);
    }
    ((float4*)g_cpart)[(s * Bsz + b) * (Esz / 4) + tid] = acc;

    // release: partial + esum + out_w globally visible from ALL warps, then signal
    __threadfence();
    __syncthreads();
    __shared__ int done;
    if (tid == 0) done = atomicAdd(&g_ctr[b], 1);
    __syncthreads();

    if (done == TSPLIT - 1) {
        __threadfence();  // acquire
        float S = 0.0f;
#pragma unroll
        for (int p = 0; p < TSPLIT; p++) S += g_esum[p * Bsz + b];
        const float inv = 1.0f / S;

        float4 sum = make_float4(0.f, 0.f, 0.f, 0.f);
#pragma unroll
        for (int p = 0; p < TSPLIT; p++) {
            float4 v = ((const float4*)g_cpart)[(p * Bsz + b) * (Esz / 4) + tid];
            sum.x += v.x; sum.y += v.y; sum.z += v.z; sum.w += v.w;
        }
        sum.x *= inv; sum.y *= inv; sum.z *= inv; sum.w *= inv;
        ((float4*)out_ctx)[b * (Esz / 4) + tid] = sum;

        for (int t = tid; t < Tsz; t += 128)
            out_w[b * Tsz + t] *= inv;

        if (tid == 0) g_ctr[b] = 0;  // reset for next replay
    }
}

// ---------------- launch --------------------------------------------------------
extern "C" void kernel_launch(void* const* d_in, const int* in_sizes, int n_in,
                              void* d_out, int out_size) {
    const float* ash  = (const float*)d_in[0];
    const float* mem  = (const float*)d_in[1];
    const float* prev = (const float*)d_in[2];
    const unsigned char* mask = (const unsigned char*)d_in[3];
    const float* W1   = (const float*)d_in[4];
    const float* b1   = (const float*)d_in[5];
    const float* W2   = (const float*)d_in[6];
    const float* Wlin = (const float*)d_in[7];
    const float* blin = (const float*)d_in[8];

    float* out     = (float*)d_out;
    float* out_ctx = out;
    float* out_w   = out + Bsz * Esz;
    float* out_loc = out_w + Bsz * Tsz;

    gemm1_kernel<<<dim3(Asz / 64, KS), 256>>>(ash, W1);
    gemm2_kernel<<<dim3(Asz / 64, KS), 256>>>(W2, b1);
    head_kernel<<<Bsz, 768>>>(Wlin, blin, prev, out_loc);
    ctx_fused_kernel<<<dim3(TSPLIT, Bsz), 128>>>(mem, mask, out_w, out_ctx);
}